// round 10
// baseline (speedup 1.0000x reference)
#include <cuda_runtime.h>
#include <cuda_bf16.h>
#include <math.h>
#include <stdint.h>

#define S_LEN   2048
#define BATCH   2
#define DMODEL  2048
#define NH      16
#define NKV     4
#define HD      128
#define M_ROWS  (BATCH * S_LEN)          // 4096
#define QCOLS   (NH * HD)                // 2048
#define KVCOLS  (NKV * HD)               // 512
#define QKVN    (QCOLS + 2 * KVCOLS)     // 3072
#define QSCALE  0.08838834764831845f

// ================= scratch =================
__device__ unsigned short g_xhi [M_ROWS * DMODEL];
__device__ unsigned short g_xlo [M_ROWS * DMODEL];
__device__ unsigned short g_ahi [M_ROWS * QCOLS];
__device__ unsigned short g_alo [M_ROWS * QCOLS];
__device__ unsigned short g_qhi [M_ROWS * QCOLS];
__device__ unsigned short g_qlo [M_ROWS * QCOLS];
__device__ unsigned short g_khi [M_ROWS * KVCOLS];
__device__ unsigned short g_klo [M_ROWS * KVCOLS];
__device__ unsigned short g_vhi [M_ROWS * KVCOLS];
__device__ unsigned short g_vlo [M_ROWS * KVCOLS];
__device__ unsigned short g_wqkvt_hi[QKVN  * DMODEL];
__device__ unsigned short g_wqkvt_lo[QKVN  * DMODEL];
__device__ unsigned short g_wot_hi  [DMODEL * QCOLS];
__device__ unsigned short g_wot_lo  [DMODEL * QCOLS];

// ================= helpers =================
__device__ __forceinline__ uint32_t smem_u32(const void* p) {
    uint32_t a;
    asm("{ .reg .u64 t; cvta.to.shared.u64 t, %1; cvt.u32.u64 %0, t; }" : "=r"(a) : "l"(p));
    return a;
}
#define CP16(s, g) \
    asm volatile("cp.async.cg.shared.global [%0], [%1], 16;" :: "r"(s), "l"(g))
#define CP_COMMIT() asm volatile("cp.async.commit_group;")
#define CP_WAIT2()  asm volatile("cp.async.wait_group 2;")
#define CP_WAIT1()  asm volatile("cp.async.wait_group 1;")
#define CP_WAIT0()  asm volatile("cp.async.wait_group 0;")
#define LDSM4(r0, r1, r2, r3, a) \
    asm volatile("ldmatrix.sync.aligned.m8n8.x4.shared.b16 {%0,%1,%2,%3}, [%4];" \
                 : "=r"(r0), "=r"(r1), "=r"(r2), "=r"(r3) : "r"(a))
#define LDSM4T(r0, r1, r2, r3, a) \
    asm volatile("ldmatrix.sync.aligned.m8n8.x4.trans.shared.b16 {%0,%1,%2,%3}, [%4];" \
                 : "=r"(r0), "=r"(r1), "=r"(r2), "=r"(r3) : "r"(a))
#define MMA16816(d, a, b) \
    asm volatile("mma.sync.aligned.m16n8k16.row.col.f32.bf16.bf16.f32 " \
                 "{%0,%1,%2,%3},{%4,%5,%6,%7},{%8,%9},{%0,%1,%2,%3};" \
                 : "+f"((d)[0]), "+f"((d)[1]), "+f"((d)[2]), "+f"((d)[3]) \
                 : "r"((a)[0]), "r"((a)[1]), "r"((a)[2]), "r"((a)[3]), \
                   "r"((b)[0]), "r"((b)[1]))

__device__ __forceinline__ uint32_t pck(__nv_bfloat16 a, __nv_bfloat16 b) {
    return ((uint32_t)*(unsigned short*)&b << 16) | (uint32_t)*(unsigned short*)&a;
}
__device__ __forceinline__ uint32_t split_pair(float a, float b, uint32_t& lo) {
    __nv_bfloat16 ha = __float2bfloat16(a), hb = __float2bfloat16(b);
    __nv_bfloat16 la = __float2bfloat16(a - __bfloat162float(ha));
    __nv_bfloat16 lb = __float2bfloat16(b - __bfloat162float(hb));
    lo = pck(la, lb);
    return pck(ha, hb);
}

// ================= split / transpose-split =================
__global__ void split_kernel(const float* __restrict__ X,
                             unsigned short* __restrict__ hi,
                             unsigned short* __restrict__ lo, int n4)
{
    int i = blockIdx.x * blockDim.x + threadIdx.x;
    if (i >= n4) return;
    float4 x = ((const float4*)X)[i];
    uint32_t l0, l1;
    uint32_t h0 = split_pair(x.x, x.y, l0);
    uint32_t h1 = split_pair(x.z, x.w, l1);
    ((uint2*)hi)[i] = make_uint2(h0, h1);
    ((uint2*)lo)[i] = make_uint2(l0, l1);
}

// W[Kd, Nd] fp32 -> Wt[Nd, Kd] bf16 hi/lo
__global__ void tsplit_kernel(const float* __restrict__ W,
                              unsigned short* __restrict__ hi,
                              unsigned short* __restrict__ lo, int Kd, int Nd)
{
    __shared__ float ts[32][33];
    const int nb = blockIdx.x * 32, kb = blockIdx.y * 32;
    const int tx = threadIdx.x, ty = threadIdx.y;   // 32 x 8
#pragma unroll
    for (int i = 0; i < 4; i++)
        ts[ty + 8 * i][tx] = W[(size_t)(kb + ty + 8 * i) * Nd + nb + tx];
    __syncthreads();
#pragma unroll
    for (int i = 0; i < 4; i++) {
        float v = ts[tx][ty + 8 * i];
        __nv_bfloat16 h = __float2bfloat16(v);
        __nv_bfloat16 l = __float2bfloat16(v - __bfloat162float(h));
        size_t o = (size_t)(nb + ty + 8 * i) * Kd + kb + tx;
        hi[o] = *(unsigned short*)&h;
        lo[o] = *(unsigned short*)&l;
    }
}

// ================= shared GEMM mainloop (3-stage cp.async) =================
#define BMM 128
#define BNN 128
#define BKK 32
#define ROWB 80
#define MATB (128 * ROWB)
#define STGB (4 * MATB)
#define GSMEM (3 * STGB)                 // 122880

#define G_LOAD(Ahi, Alo, Bhi, Blo, K, kt, st) do {                                \
    uint32_t s0 = sb + (st) * STGB + lr * ROWB + lc * 16;                         \
    size_t gA = (size_t)(row0 + lr) * (K) + (kt) * BKK + lc * 8;                  \
    size_t gB = (size_t)(col0 + lr) * (K) + (kt) * BKK + lc * 8;                  \
    size_t g64 = (size_t)64 * (K);                                                \
    CP16(s0,                        Ahi + gA);                                    \
    CP16(s0 + 64 * ROWB,            Ahi + gA + g64);                              \
    CP16(s0 + MATB,                 Alo + gA);                                    \
    CP16(s0 + MATB + 64 * ROWB,     Alo + gA + g64);                              \
    CP16(s0 + 2 * MATB,             Bhi + gB);                                    \
    CP16(s0 + 2 * MATB + 64 * ROWB, Bhi + gB + g64);                              \
    CP16(s0 + 3 * MATB,             Blo + gB);                                    \
    CP16(s0 + 3 * MATB + 64 * ROWB, Blo + gB + g64);                              \
} while (0)

#define GEMM_BODY(Ahi, Alo, Bhi, Blo, K)                                          \
    extern __shared__ char smem[];                                                \
    const uint32_t sb = smem_u32(smem);                                           \
    const int tid = threadIdx.x;                                                  \
    const int lid = tid & 31;                                                     \
    const int wid = tid >> 5;                                                     \
    const int row0 = blockIdx.y * BMM;                                            \
    const int col0 = blockIdx.x * BNN;                                            \
    const int wm0 = (wid >> 2) * 64;                                              \
    const int wn0 = (wid & 3) * 32;                                               \
    const int lr = tid >> 2;                                                      \
    const int lc = tid & 3;                                                       \
    float acc[4][4][4];                                                           \
    _Pragma("unroll")                                                             \
    for (int mi = 0; mi < 4; mi++)                                                \
        _Pragma("unroll")                                                         \
        for (int ni = 0; ni < 4; ni++)                                            \
            _Pragma("unroll")                                                     \
            for (int c = 0; c < 4; c++) acc[mi][ni][c] = 0.f;                     \
    const int NIT = (K) / BKK;                                                    \
    G_LOAD(Ahi, Alo, Bhi, Blo, K, 0, 0); CP_COMMIT();                             \
    G_LOAD(Ahi, Alo, Bhi, Blo, K, 1, 1); CP_COMMIT();                             \
    int cur = 0;                                                                  \
    for (int it = 0; it < NIT; ++it) {                                            \
        if (it + 2 < NIT) {                                                       \
            int nx = cur + 2; if (nx >= 3) nx -= 3;                               \
            G_LOAD(Ahi, Alo, Bhi, Blo, K, it + 2, nx);                            \
            CP_COMMIT(); CP_WAIT2();                                              \
        } else if (it + 1 < NIT) { CP_WAIT1(); }                                  \
        else                     { CP_WAIT0(); }                                  \
        __syncthreads();                                                          \
        const uint32_t base = sb + cur * STGB;                                    \
        _Pragma("unroll")                                                         \
        for (int ks = 0; ks < 2; ++ks) {                                          \
            uint32_t ah[4][4], al[4][4], bh[4][2], bl[4][2];                      \
            _Pragma("unroll")                                                     \
            for (int mi = 0; mi < 4; mi++) {                                      \
                uint32_t addr = base + (wm0 + mi * 16 + (lid & 15)) * ROWB        \
                              + (ks * 2 + (lid >> 4)) * 16;                       \
                LDSM4(ah[mi][0], ah[mi][1], ah[mi][2], ah[mi][3], addr);          \
                LDSM4(al[mi][0], al[mi][1], al[mi][2], al[mi][3], addr + MATB);   \
            }                                                                     \
            _Pragma("unroll")                                                     \
            for (int j = 0; j < 2; j++) {                                         \
                int brow = wn0 + j * 16 + (lid & 7) + ((lid >> 4) << 3);          \
                uint32_t addr = base + 2 * MATB + brow * ROWB                     \
                              + (ks * 2 + ((lid >> 3) & 1)) * 16;                 \
                uint32_t t0, t1, t2, t3;                                          \
                LDSM4(t0, t1, t2, t3, addr);                                      \
                bh[2 * j][0] = t0; bh[2 * j][1] = t1;                             \
                bh[2 * j + 1][0] = t2; bh[2 * j + 1][1] = t3;                     \
                LDSM4(t0, t1, t2, t3, addr + MATB);                               \
                bl[2 * j][0] = t0; bl[2 * j][1] = t1;                             \
                bl[2 * j + 1][0] = t2; bl[2 * j + 1][1] = t3;                     \
            }                                                                     \
            _Pragma("unroll")                                                     \
            for (int mi = 0; mi < 4; mi++)                                        \
                _Pragma("unroll")                                                 \
                for (int ni = 0; ni < 4; ni++) {                                  \
                    MMA16816(acc[mi][ni], ah[mi], bh[ni]);                        \
                    MMA16816(acc[mi][ni], ah[mi], bl[ni]);                        \
                    MMA16816(acc[mi][ni], al[mi], bh[ni]);                        \
                }                                                                 \
        }                                                                         \
        __syncthreads();                                                          \
        cur = (cur + 1 == 3) ? 0 : cur + 1;                                       \
    }

// ---- out-projection GEMM: plain fp32 store
__global__ void __launch_bounds__(256, 1) gemm_out_kernel(
    const unsigned short* __restrict__ Ahi, const unsigned short* __restrict__ Alo,
    const unsigned short* __restrict__ Bhi, const unsigned short* __restrict__ Blo,
    float* __restrict__ C, int N, int K)
{
    GEMM_BODY(Ahi, Alo, Bhi, Blo, K)
    const int qid = lid >> 2, tq = lid & 3;
#pragma unroll
    for (int mi = 0; mi < 4; mi++)
#pragma unroll
        for (int ni = 0; ni < 4; ni++) {
            int r = row0 + wm0 + mi * 16 + qid;
            int c = col0 + wn0 + ni * 8 + tq * 2;
            *(float2*)&C[(size_t)r * N + c] =
                make_float2(acc[mi][ni][0], acc[mi][ni][1]);
            *(float2*)&C[(size_t)(r + 8) * N + c] =
                make_float2(acc[mi][ni][2], acc[mi][ni][3]);
        }
}

// ---- fused QKV GEMM: epilogue applies rope (+scale for q) and split-writes bf16
__global__ void __launch_bounds__(256, 1) gemm_qkv_kernel(
    const unsigned short* __restrict__ Ahi, const unsigned short* __restrict__ Alo,
    const unsigned short* __restrict__ Bhi, const unsigned short* __restrict__ Blo,
    const float* __restrict__ cs, const float* __restrict__ sn,
    unsigned short* __restrict__ qhi, unsigned short* __restrict__ qlo,
    unsigned short* __restrict__ khi, unsigned short* __restrict__ klo,
    unsigned short* __restrict__ vhi, unsigned short* __restrict__ vlo)
{
    GEMM_BODY(Ahi, Alo, Bhi, Blo, DMODEL)
    const int qid = lid >> 2, tq = lid & 3;
    const bool isV = (col0 >= QCOLS + KVCOLS);
    const bool isQ = (col0 < QCOLS);

    if (isV) {
#pragma unroll
        for (int mi = 0; mi < 4; mi++)
#pragma unroll
            for (int ni = 0; ni < 4; ni++) {
                int r = row0 + wm0 + mi * 16 + qid;
                int c = col0 - (QCOLS + KVCOLS) + wn0 + ni * 8 + tq * 2;
                uint32_t l0, l1;
                uint32_t h0 = split_pair(acc[mi][ni][0], acc[mi][ni][1], l0);
                uint32_t h1 = split_pair(acc[mi][ni][2], acc[mi][ni][3], l1);
                *(uint32_t*)(vhi + (size_t)r * KVCOLS + c) = h0;
                *(uint32_t*)(vlo + (size_t)r * KVCOLS + c) = l0;
                *(uint32_t*)(vhi + (size_t)(r + 8) * KVCOLS + c) = h1;
                *(uint32_t*)(vlo + (size_t)(r + 8) * KVCOLS + c) = l1;
            }
    } else {
        unsigned short* dh = isQ ? qhi : khi;
        unsigned short* dl = isQ ? qlo : klo;
        const int dcols = isQ ? QCOLS : KVCOLS;
        const int cbase = isQ ? col0 : col0 - QCOLS;
        const float scale = isQ ? QSCALE : 1.0f;
#pragma unroll
        for (int mi = 0; mi < 4; mi++) {
            int r = row0 + wm0 + mi * 16 + qid;
            int s0 = r & (S_LEN - 1);
            int s1 = (r + 8) & (S_LEN - 1);
#pragma unroll
            for (int ni = 0; ni < 4; ni++) {
                int c = cbase + wn0 + ni * 8 + tq * 2;
                int d2 = (c & 127) >> 1;
                float c0 = cs[s0 * 64 + d2], t0 = sn[s0 * 64 + d2];
                float c1 = cs[s1 * 64 + d2], t1 = sn[s1 * 64 + d2];
                float a0 = acc[mi][ni][0], a1 = acc[mi][ni][1];
                float a2 = acc[mi][ni][2], a3 = acc[mi][ni][3];
                float e0 = (a0 * c0 - a1 * t0) * scale;
                float e1 = (a0 * t0 + a1 * c0) * scale;
                float f0 = (a2 * c1 - a3 * t1) * scale;
                float f1 = (a2 * t1 + a3 * c1) * scale;
                uint32_t l0, l1;
                uint32_t h0 = split_pair(e0, e1, l0);
                uint32_t h1 = split_pair(f0, f1, l1);
                *(uint32_t*)(dh + (size_t)r * dcols + c) = h0;
                *(uint32_t*)(dl + (size_t)r * dcols + c) = l0;
                *(uint32_t*)(dh + (size_t)(r + 8) * dcols + c) = h1;
                *(uint32_t*)(dl + (size_t)(r + 8) * dcols + c) = l1;
            }
        }
    }
}

// ================= tensor-core flash attention, BN=64 =================
#define AQ_STR   272
#define AT_MAT   (64 * AQ_STR)       // 17408
#define AT_STAGE (4 * AT_MAT)        // 69632
#define AT_SMEM  (2 * AT_STAGE)      // 139264

__global__ void __launch_bounds__(256, 1) flash_mma_kernel(
    const unsigned short* __restrict__ qhi, const unsigned short* __restrict__ qlo,
    const unsigned short* __restrict__ khi, const unsigned short* __restrict__ klo,
    const unsigned short* __restrict__ vhi, const unsigned short* __restrict__ vlo,
    unsigned short* __restrict__ ohi, unsigned short* __restrict__ olo)
{
    extern __shared__ char smem[];
    const uint32_t sb = smem_u32(smem);
    const int tid = threadIdx.x;
    const int lid = tid & 31;
    const int wid = tid >> 5;
    const int qt = (int)gridDim.x - 1 - (int)blockIdx.x;
    const int h  = blockIdx.y;
    const int b  = blockIdx.z;
    const int g  = h >> 2;
    const int q0 = qt * 128;
    const int wm = wid * 16;

    // ---- prologue: Q hi/lo -> smem -> frags
    const unsigned short* qh = qhi + ((size_t)(b * S_LEN + q0)) * QCOLS + h * HD;
    const unsigned short* ql = qlo + ((size_t)(b * S_LEN + q0)) * QCOLS + h * HD;
#pragma unroll
    for (int i = 0; i < 8; i++) {
        int cid = tid + 256 * i;
        int r = cid >> 4, c = cid & 15;
        uint32_t d = sb + r * AQ_STR + c * 16;
        size_t go = (size_t)r * QCOLS + c * 8;
        CP16(d, qh + go);
        CP16(d + AT_STAGE, ql + go);
    }
    CP_COMMIT(); CP_WAIT0();
    __syncthreads();

    uint32_t qfh[8][4], qfl[8][4];
#pragma unroll
    for (int kc = 0; kc < 8; kc++) {
        uint32_t addr = sb + (wm + (lid & 15)) * AQ_STR + (kc * 2 + (lid >> 4)) * 16;
        LDSM4(qfh[kc][0], qfh[kc][1], qfh[kc][2], qfh[kc][3], addr);
        LDSM4(qfl[kc][0], qfl[kc][1], qfl[kc][2], qfl[kc][3], addr + AT_STAGE);
    }
    __syncthreads();

    float o[16][4];
#pragma unroll
    for (int ni = 0; ni < 16; ni++)
#pragma unroll
        for (int c = 0; c < 4; c++) o[ni][c] = 0.f;
    float lsum0 = 0.f, lsum1 = 0.f;

    const unsigned short* kh = khi + (size_t)(b * S_LEN) * KVCOLS + g * HD;
    const unsigned short* kl = klo + (size_t)(b * S_LEN) * KVCOLS + g * HD;
    const unsigned short* vh = vhi + (size_t)(b * S_LEN) * KVCOLS + g * HD;
    const unsigned short* vl = vlo + (size_t)(b * S_LEN) * KVCOLS + g * HD;

    const int NKT = (qt + 1) * 2;

#define AT_LOAD(kt, st) do {                                                      \
    _Pragma("unroll")                                                             \
    for (int i = 0; i < 4; i++) {                                                 \
        int cid = tid + 256 * i;                                                  \
        int r = cid >> 4, c = cid & 15;                                           \
        uint32_t d = sb + (st) * AT_STAGE + r * AQ_STR + c * 16;                  \
        size_t go = (size_t)((kt) * 64 + r) * KVCOLS + c * 8;                     \
        CP16(d,              kh + go);                                            \
        CP16(d + AT_MAT,     kl + go);                                            \
        CP16(d + 2 * AT_MAT, vh + go);                                            \
        CP16(d + 3 * AT_MAT, vl + go);                                            \
    }                                                                             \
} while (0)

    AT_LOAD(0, 0);
    CP_COMMIT();

    const int r0 = q0 + wm + (lid >> 2);
    const int r1 = r0 + 8;

    for (int it = 0; it < NKT; ++it) {
        const int cur = it & 1;
        if (it + 1 < NKT) { AT_LOAD(it + 1, cur ^ 1); CP_COMMIT(); CP_WAIT1(); }
        else              { CP_WAIT0(); }
        __syncthreads();

        const int kv0 = it * 64;
        if (kv0 <= q0 + wm + 15) {
            const uint32_t base = sb + cur * AT_STAGE;

            // ---- S = Q @ K^T (3-term), j-outer to keep B frags transient
            float s[8][4];
#pragma unroll
            for (int ni = 0; ni < 8; ni++)
#pragma unroll
                for (int c = 0; c < 4; c++) s[ni][c] = 0.f;

#pragma unroll
            for (int j = 0; j < 4; j++) {
                int brow = j * 16 + (lid & 7) + ((lid >> 4) << 3);
#pragma unroll
                for (int kc = 0; kc < 8; kc++) {
                    uint32_t addr = base + brow * AQ_STR
                                  + kc * 32 + ((lid >> 3) & 1) * 16;
                    uint32_t t0, t1, t2, t3;
                    LDSM4(t0, t1, t2, t3, addr);
                    uint32_t bh0[2] = {t0, t1}, bh1[2] = {t2, t3};
                    LDSM4(t0, t1, t2, t3, addr + AT_MAT);
                    uint32_t bl0[2] = {t0, t1}, bl1[2] = {t2, t3};
                    MMA16816(s[2 * j],     qfh[kc], bh0);
                    MMA16816(s[2 * j],     qfh[kc], bl0);
                    MMA16816(s[2 * j],     qfl[kc], bh0);
                    MMA16816(s[2 * j + 1], qfh[kc], bh1);
                    MMA16816(s[2 * j + 1], qfh[kc], bl1);
                    MMA16816(s[2 * j + 1], qfl[kc], bh1);
                }
            }

            // ---- mask + exp + split-pack P (P is 16 x 64 -> pa[4][4])
            const bool need_mask = (kv0 + 63 > q0 + wm);
            uint32_t pa_h[4][4], pa_l[4][4];
#pragma unroll
            for (int ni = 0; ni < 8; ni++) {
                float s0 = fminf(s[ni][0], 60.f), s1 = fminf(s[ni][1], 60.f);
                float s2 = fminf(s[ni][2], 60.f), s3 = fminf(s[ni][3], 60.f);
                float p0, p1, p2, p3;
                if (need_mask) {
                    int cb = kv0 + ni * 8 + ((lid & 3) << 1);
                    p0 = (cb     <= r0) ? __expf(s0) : 0.f;
                    p1 = (cb + 1 <= r0) ? __expf(s1) : 0.f;
                    p2 = (cb     <= r1) ? __expf(s2) : 0.f;
                    p3 = (cb + 1 <= r1) ? __expf(s3) : 0.f;
                } else {
                    p0 = __expf(s0); p1 = __expf(s1);
                    p2 = __expf(s2); p3 = __expf(s3);
                }
                lsum0 += p0 + p1;
                lsum1 += p2 + p3;
                uint32_t lp01, lp23;
                uint32_t hp01 = split_pair(p0, p1, lp01);
                uint32_t hp23 = split_pair(p2, p3, lp23);
                int kc2 = ni >> 1, sel = (ni & 1) * 2;
                pa_h[kc2][sel]     = hp01;
                pa_h[kc2][sel + 1] = hp23;
                pa_l[kc2][sel]     = lp01;
                pa_l[kc2][sel + 1] = lp23;
            }

            // ---- O += P @ V (3-term), V via ldmatrix.trans; kc2-inner
            const int gq = lid >> 3;
            const int vr = (gq & 1) * 8 + (lid & 7);
            const int vc = (gq >> 1) * 8;
#pragma unroll
            for (int j = 0; j < 8; j++) {
#pragma unroll
                for (int kc2 = 0; kc2 < 4; kc2++) {
                    uint32_t addr = base + 2 * AT_MAT
                                  + (kc2 * 16 + vr) * AQ_STR + (j * 16 + vc) * 2;
                    uint32_t t0, t1, t2, t3;
                    LDSM4T(t0, t1, t2, t3, addr);
                    uint32_t vb0[2] = {t0, t1}, vb1[2] = {t2, t3};
                    LDSM4T(t0, t1, t2, t3, addr + AT_MAT);
                    uint32_t wb0[2] = {t0, t1}, wb1[2] = {t2, t3};
                    MMA16816(o[2 * j],     pa_h[kc2], vb0);
                    MMA16816(o[2 * j],     pa_h[kc2], wb0);
                    MMA16816(o[2 * j],     pa_l[kc2], vb0);
                    MMA16816(o[2 * j + 1], pa_h[kc2], vb1);
                    MMA16816(o[2 * j + 1], pa_h[kc2], wb1);
                    MMA16816(o[2 * j + 1], pa_l[kc2], vb1);
                }
            }
        }
        __syncthreads();
    }
#undef AT_LOAD

    // ---- normalize + split-write O
    lsum0 += __shfl_xor_sync(0xffffffffu, lsum0, 1);
    lsum0 += __shfl_xor_sync(0xffffffffu, lsum0, 2);
    lsum1 += __shfl_xor_sync(0xffffffffu, lsum1, 1);
    lsum1 += __shfl_xor_sync(0xffffffffu, lsum1, 2);
    const float inv0 = 1.f / lsum0, inv1 = 1.f / lsum1;

    size_t r0g = (size_t)(b * S_LEN + r0) * QCOLS + h * HD;
    size_t r1g = r0g + (size_t)8 * QCOLS;
#pragma unroll
    for (int ni = 0; ni < 16; ni++) {
        int c = ni * 8 + ((lid & 3) << 1);
        uint32_t l0, l1;
        uint32_t h0 = split_pair(o[ni][0] * inv0, o[ni][1] * inv0, l0);
        uint32_t h1 = split_pair(o[ni][2] * inv1, o[ni][3] * inv1, l1);
        *(uint32_t*)(ohi + r0g + c) = h0;
        *(uint32_t*)(olo + r0g + c) = l0;
        *(uint32_t*)(ohi + r1g + c) = h1;
        *(uint32_t*)(olo + r1g + c) = l1;
    }
}

// ================= launch =================
extern "C" void kernel_launch(void* const* d_in, const int* in_sizes, int n_in,
                              void* d_out, int out_size)
{
    (void)in_sizes; (void)n_in; (void)out_size;
    const float* x  = (const float*)d_in[0];
    const float* fc = (const float*)d_in[1];
    const float* fs = (const float*)d_in[2];
    const float* wq = (const float*)d_in[3];
    const float* wk = (const float*)d_in[4];
    const float* wv = (const float*)d_in[5];
    const float* wo = (const float*)d_in[6];
    float* out = (float*)d_out;

    unsigned short *xhi, *xlo, *ahi, *alo, *qhi, *qlo, *khi, *klo, *vhi, *vlo;
    unsigned short *wqkvh, *wqkvl, *woh, *wol;
    cudaGetSymbolAddress((void**)&xhi,   g_xhi);
    cudaGetSymbolAddress((void**)&xlo,   g_xlo);
    cudaGetSymbolAddress((void**)&ahi,   g_ahi);
    cudaGetSymbolAddress((void**)&alo,   g_alo);
    cudaGetSymbolAddress((void**)&qhi,   g_qhi);
    cudaGetSymbolAddress((void**)&qlo,   g_qlo);
    cudaGetSymbolAddress((void**)&khi,   g_khi);
    cudaGetSymbolAddress((void**)&klo,   g_klo);
    cudaGetSymbolAddress((void**)&vhi,   g_vhi);
    cudaGetSymbolAddress((void**)&vlo,   g_vlo);
    cudaGetSymbolAddress((void**)&wqkvh, g_wqkvt_hi);
    cudaGetSymbolAddress((void**)&wqkvl, g_wqkvt_lo);
    cudaGetSymbolAddress((void**)&woh,   g_wot_hi);
    cudaGetSymbolAddress((void**)&wol,   g_wot_lo);

    cudaFuncSetAttribute(gemm_qkv_kernel,
                         cudaFuncAttributeMaxDynamicSharedMemorySize, GSMEM);
    cudaFuncSetAttribute(gemm_out_kernel,
                         cudaFuncAttributeMaxDynamicSharedMemorySize, GSMEM);
    cudaFuncSetAttribute(flash_mma_kernel,
                         cudaFuncAttributeMaxDynamicSharedMemorySize, AT_SMEM);

    // 1) split x; transpose-split weights into packed [wq|wk|wv] and wo
    {
        int n4 = M_ROWS * DMODEL / 4;
        split_kernel<<<(n4 + 255) / 256, 256>>>(x, xhi, xlo, n4);
        tsplit_kernel<<<dim3(QCOLS / 32,  DMODEL / 32), dim3(32, 8)>>>(
            wq, wqkvh, wqkvl, DMODEL, QCOLS);
        tsplit_kernel<<<dim3(KVCOLS / 32, DMODEL / 32), dim3(32, 8)>>>(
            wk, wqkvh + (size_t)QCOLS * DMODEL, wqkvl + (size_t)QCOLS * DMODEL,
            DMODEL, KVCOLS);
        tsplit_kernel<<<dim3(KVCOLS / 32, DMODEL / 32), dim3(32, 8)>>>(
            wv, wqkvh + (size_t)(QCOLS + KVCOLS) * DMODEL,
            wqkvl + (size_t)(QCOLS + KVCOLS) * DMODEL, DMODEL, KVCOLS);
        tsplit_kernel<<<dim3(DMODEL / 32, QCOLS / 32),  dim3(32, 8)>>>(
            wo, woh, wol, QCOLS, DMODEL);
    }

    // 2) fused QKV projection + rope + split epilogue
    gemm_qkv_kernel<<<dim3(QKVN / BNN, M_ROWS / BMM), 256, GSMEM>>>(
        xhi, xlo, wqkvh, wqkvl, fc, fs, qhi, qlo, khi, klo, vhi, vlo);

    // 3) tensor-core flash attention (split O out)
    flash_mma_kernel<<<dim3(S_LEN / 128, NH, BATCH), 256, AT_SMEM>>>(
        qhi, qlo, khi, klo, vhi, vlo, ahi, alo);

    // 4) out projection
    gemm_out_kernel<<<dim3(DMODEL / BNN, M_ROWS / BMM), 256, GSMEM>>>(
        ahi, alo, woh, wol, out, DMODEL, DMODEL);
}

// round 11
// speedup vs baseline: 1.0144x; 1.0144x over previous
#include <cuda_runtime.h>
#include <cuda_bf16.h>
#include <math.h>
#include <stdint.h>

#define S_LEN   2048
#define BATCH   2
#define DMODEL  2048
#define NH      16
#define NKV     4
#define HD      128
#define M_ROWS  (BATCH * S_LEN)          // 4096
#define QCOLS   (NH * HD)                // 2048
#define KVCOLS  (NKV * HD)               // 512
#define QKVN    (QCOLS + 2 * KVCOLS)     // 3072
#define QSCALE  0.08838834764831845f

// ================= scratch =================
__device__ unsigned short g_xhi [M_ROWS * DMODEL];
__device__ unsigned short g_xlo [M_ROWS * DMODEL];
__device__ unsigned short g_ahi [M_ROWS * QCOLS];
__device__ unsigned short g_alo [M_ROWS * QCOLS];
__device__ unsigned short g_qhi [M_ROWS * QCOLS];
__device__ unsigned short g_qlo [M_ROWS * QCOLS];
__device__ unsigned short g_khi [M_ROWS * KVCOLS];
__device__ unsigned short g_klo [M_ROWS * KVCOLS];
__device__ unsigned short g_vhi [M_ROWS * KVCOLS];
__device__ unsigned short g_vlo [M_ROWS * KVCOLS];
__device__ unsigned short g_wqkvt_hi[QKVN  * DMODEL];
__device__ unsigned short g_wqkvt_lo[QKVN  * DMODEL];
__device__ unsigned short g_wot_hi  [DMODEL * QCOLS];
__device__ unsigned short g_wot_lo  [DMODEL * QCOLS];

// ================= helpers =================
__device__ __forceinline__ uint32_t smem_u32(const void* p) {
    uint32_t a;
    asm("{ .reg .u64 t; cvta.to.shared.u64 t, %1; cvt.u32.u64 %0, t; }" : "=r"(a) : "l"(p));
    return a;
}
#define CP16(s, g) \
    asm volatile("cp.async.cg.shared.global [%0], [%1], 16;" :: "r"(s), "l"(g))
#define CP_COMMIT() asm volatile("cp.async.commit_group;")
#define CP_WAIT1()  asm volatile("cp.async.wait_group 1;")
#define CP_WAIT0()  asm volatile("cp.async.wait_group 0;")
#define LDSM4(r0, r1, r2, r3, a) \
    asm volatile("ldmatrix.sync.aligned.m8n8.x4.shared.b16 {%0,%1,%2,%3}, [%4];" \
                 : "=r"(r0), "=r"(r1), "=r"(r2), "=r"(r3) : "r"(a))
#define LDSM4T(r0, r1, r2, r3, a) \
    asm volatile("ldmatrix.sync.aligned.m8n8.x4.trans.shared.b16 {%0,%1,%2,%3}, [%4];" \
                 : "=r"(r0), "=r"(r1), "=r"(r2), "=r"(r3) : "r"(a))
#define MMA16816(d, a, b) \
    asm volatile("mma.sync.aligned.m16n8k16.row.col.f32.bf16.bf16.f32 " \
                 "{%0,%1,%2,%3},{%4,%5,%6,%7},{%8,%9},{%0,%1,%2,%3};" \
                 : "+f"((d)[0]), "+f"((d)[1]), "+f"((d)[2]), "+f"((d)[3]) \
                 : "r"((a)[0]), "r"((a)[1]), "r"((a)[2]), "r"((a)[3]), \
                   "r"((b)[0]), "r"((b)[1]))

__device__ __forceinline__ uint32_t pck(__nv_bfloat16 a, __nv_bfloat16 b) {
    return ((uint32_t)*(unsigned short*)&b << 16) | (uint32_t)*(unsigned short*)&a;
}
__device__ __forceinline__ uint32_t split_pair(float a, float b, uint32_t& lo) {
    __nv_bfloat16 ha = __float2bfloat16(a), hb = __float2bfloat16(b);
    __nv_bfloat16 la = __float2bfloat16(a - __bfloat162float(ha));
    __nv_bfloat16 lb = __float2bfloat16(b - __bfloat162float(hb));
    lo = pck(la, lb);
    return pck(ha, hb);
}

// ================= split x =================
__global__ void split_kernel(const float* __restrict__ X,
                             unsigned short* __restrict__ hi,
                             unsigned short* __restrict__ lo, int n4)
{
    int i = blockIdx.x * blockDim.x + threadIdx.x;
    if (i >= n4) return;
    float4 x = ((const float4*)X)[i];
    uint32_t l0, l1;
    uint32_t h0 = split_pair(x.x, x.y, l0);
    uint32_t h1 = split_pair(x.z, x.w, l1);
    ((uint2*)hi)[i] = make_uint2(h0, h1);
    ((uint2*)lo)[i] = make_uint2(l0, l1);
}

// ================= fused transpose-split of all 4 weights =================
// One launch: block id decodes which weight + which 32x32 tile.
// wq: 4096 blocks (64x64), wk: 1024, wv: 1024, wo: 4096 -> total 10240.
__device__ __forceinline__ void tsplit_tile(
    const float* __restrict__ W, unsigned short* __restrict__ hi,
    unsigned short* __restrict__ lo, int Kd, int Nd, int nb, int kb,
    float (*ts)[33])
{
    const int tx = threadIdx.x, ty = threadIdx.y;   // 32 x 8
#pragma unroll
    for (int i = 0; i < 4; i++)
        ts[ty + 8 * i][tx] = W[(size_t)(kb + ty + 8 * i) * Nd + nb + tx];
    __syncthreads();
#pragma unroll
    for (int i = 0; i < 4; i++) {
        float v = ts[tx][ty + 8 * i];
        __nv_bfloat16 h = __float2bfloat16(v);
        __nv_bfloat16 l = __float2bfloat16(v - __bfloat162float(h));
        size_t o = (size_t)(nb + ty + 8 * i) * Kd + kb + tx;
        hi[o] = *(unsigned short*)&h;
        lo[o] = *(unsigned short*)&l;
    }
}

__global__ void tsplit_all_kernel(
    const float* __restrict__ wq, const float* __restrict__ wk,
    const float* __restrict__ wv, const float* __restrict__ wo,
    unsigned short* __restrict__ wqkvh, unsigned short* __restrict__ wqkvl,
    unsigned short* __restrict__ woh,  unsigned short* __restrict__ wol)
{
    __shared__ float ts[32][33];
    int id = blockIdx.x;
    if (id < 4096) {                       // wq: [DMODEL, QCOLS] -> wqkv[0:2048]
        int nb = (id & 63) * 32, kb = (id >> 6) * 32;
        tsplit_tile(wq, wqkvh, wqkvl, DMODEL, QCOLS, nb, kb, ts);
    } else if (id < 5120) {                // wk -> wqkv rows 2048..2559
        id -= 4096;
        int nb = (id & 15) * 32, kb = (id >> 4) * 32;
        tsplit_tile(wk, wqkvh + (size_t)QCOLS * DMODEL,
                    wqkvl + (size_t)QCOLS * DMODEL, DMODEL, KVCOLS, nb, kb, ts);
    } else if (id < 6144) {                // wv -> wqkv rows 2560..3071
        id -= 5120;
        int nb = (id & 15) * 32, kb = (id >> 4) * 32;
        tsplit_tile(wv, wqkvh + (size_t)(QCOLS + KVCOLS) * DMODEL,
                    wqkvl + (size_t)(QCOLS + KVCOLS) * DMODEL, DMODEL, KVCOLS, nb, kb, ts);
    } else {                               // wo: [QCOLS, DMODEL]
        id -= 6144;
        int nb = (id & 63) * 32, kb = (id >> 6) * 32;
        tsplit_tile(wo, woh, wol, QCOLS, DMODEL, nb, kb, ts);
    }
}

// ================= shared GEMM mainloop (2-stage, proven R8) =================
#define BMM 128
#define BNN 128
#define BKK 32
#define ROWB 80
#define MATB (128 * ROWB)
#define STGB (4 * MATB)
#define GSMEM (2 * STGB)

#define GEMM_BODY(Ahi, Alo, Bhi, Blo, K)                                          \
    extern __shared__ char smem[];                                                \
    const uint32_t sb = smem_u32(smem);                                           \
    const int tid = threadIdx.x;                                                  \
    const int lid = tid & 31;                                                     \
    const int wid = tid >> 5;                                                     \
    const int row0 = blockIdx.y * BMM;                                            \
    const int col0 = blockIdx.x * BNN;                                            \
    const int wm0 = (wid >> 2) * 64;                                              \
    const int wn0 = (wid & 3) * 32;                                               \
    const int lr = tid >> 2;                                                      \
    const int lc = tid & 3;                                                       \
    float acc[4][4][4];                                                           \
    _Pragma("unroll")                                                             \
    for (int mi = 0; mi < 4; mi++)                                                \
        _Pragma("unroll")                                                         \
        for (int ni = 0; ni < 4; ni++)                                            \
            _Pragma("unroll")                                                     \
            for (int c = 0; c < 4; c++) acc[mi][ni][c] = 0.f;                     \
    const int NIT = (K) / BKK;                                                    \
    {                                                                             \
        uint32_t s0 = sb + lr * ROWB + lc * 16;                                   \
        size_t gA = (size_t)(row0 + lr) * (K) + lc * 8;                           \
        size_t gB = (size_t)(col0 + lr) * (K) + lc * 8;                           \
        size_t g64 = (size_t)64 * (K);                                            \
        CP16(s0,                        Ahi + gA);                                \
        CP16(s0 + 64 * ROWB,            Ahi + gA + g64);                          \
        CP16(s0 + MATB,                 Alo + gA);                                \
        CP16(s0 + MATB + 64 * ROWB,     Alo + gA + g64);                          \
        CP16(s0 + 2 * MATB,             Bhi + gB);                                \
        CP16(s0 + 2 * MATB + 64 * ROWB, Bhi + gB + g64);                          \
        CP16(s0 + 3 * MATB,             Blo + gB);                                \
        CP16(s0 + 3 * MATB + 64 * ROWB, Blo + gB + g64);                          \
    }                                                                             \
    CP_COMMIT();                                                                  \
    for (int it = 0; it < NIT; ++it) {                                            \
        const int cur = it & 1;                                                   \
        if (it + 1 < NIT) {                                                       \
            uint32_t s0 = sb + (cur ^ 1) * STGB + lr * ROWB + lc * 16;            \
            size_t gA = (size_t)(row0 + lr) * (K) + (it + 1) * BKK + lc * 8;      \
            size_t gB = (size_t)(col0 + lr) * (K) + (it + 1) * BKK + lc * 8;      \
            size_t g64 = (size_t)64 * (K);                                        \
            CP16(s0,                        Ahi + gA);                            \
            CP16(s0 + 64 * ROWB,            Ahi + gA + g64);                      \
            CP16(s0 + MATB,                 Alo + gA);                            \
            CP16(s0 + MATB + 64 * ROWB,     Alo + gA + g64);                      \
            CP16(s0 + 2 * MATB,             Bhi + gB);                            \
            CP16(s0 + 2 * MATB + 64 * ROWB, Bhi + gB + g64);                      \
            CP16(s0 + 3 * MATB,             Blo + gB);                            \
            CP16(s0 + 3 * MATB + 64 * ROWB, Blo + gB + g64);                      \
            CP_COMMIT(); CP_WAIT1();                                              \
        } else { CP_WAIT0(); }                                                    \
        __syncthreads();                                                          \
        const uint32_t base = sb + cur * STGB;                                    \
        _Pragma("unroll")                                                         \
        for (int ks = 0; ks < 2; ++ks) {                                          \
            uint32_t ah[4][4], al[4][4], bh[4][2], bl[4][2];                      \
            _Pragma("unroll")                                                     \
            for (int mi = 0; mi < 4; mi++) {                                      \
                uint32_t addr = base + (wm0 + mi * 16 + (lid & 15)) * ROWB        \
                              + (ks * 2 + (lid >> 4)) * 16;                       \
                LDSM4(ah[mi][0], ah[mi][1], ah[mi][2], ah[mi][3], addr);          \
                LDSM4(al[mi][0], al[mi][1], al[mi][2], al[mi][3], addr + MATB);   \
            }                                                                     \
            _Pragma("unroll")                                                     \
            for (int j = 0; j < 2; j++) {                                         \
                int brow = wn0 + j * 16 + (lid & 7) + ((lid >> 4) << 3);          \
                uint32_t addr = base + 2 * MATB + brow * ROWB                     \
                              + (ks * 2 + ((lid >> 3) & 1)) * 16;                 \
                uint32_t t0, t1, t2, t3;                                          \
                LDSM4(t0, t1, t2, t3, addr);                                      \
                bh[2 * j][0] = t0; bh[2 * j][1] = t1;                             \
                bh[2 * j + 1][0] = t2; bh[2 * j + 1][1] = t3;                     \
                LDSM4(t0, t1, t2, t3, addr + MATB);                               \
                bl[2 * j][0] = t0; bl[2 * j][1] = t1;                             \
                bl[2 * j + 1][0] = t2; bl[2 * j + 1][1] = t3;                     \
            }                                                                     \
            _Pragma("unroll")                                                     \
            for (int mi = 0; mi < 4; mi++)                                        \
                _Pragma("unroll")                                                 \
                for (int ni = 0; ni < 4; ni++) {                                  \
                    MMA16816(acc[mi][ni], ah[mi], bh[ni]);                        \
                    MMA16816(acc[mi][ni], ah[mi], bl[ni]);                        \
                    MMA16816(acc[mi][ni], al[mi], bh[ni]);                        \
                }                                                                 \
        }                                                                         \
        __syncthreads();                                                          \
    }

// ---- out-projection GEMM: plain fp32 store
__global__ void __launch_bounds__(256, 1) gemm_out_kernel(
    const unsigned short* __restrict__ Ahi, const unsigned short* __restrict__ Alo,
    const unsigned short* __restrict__ Bhi, const unsigned short* __restrict__ Blo,
    float* __restrict__ C, int N, int K)
{
    GEMM_BODY(Ahi, Alo, Bhi, Blo, K)
    const int qid = lid >> 2, tq = lid & 3;
#pragma unroll
    for (int mi = 0; mi < 4; mi++)
#pragma unroll
        for (int ni = 0; ni < 4; ni++) {
            int r = row0 + wm0 + mi * 16 + qid;
            int c = col0 + wn0 + ni * 8 + tq * 2;
            *(float2*)&C[(size_t)r * N + c] =
                make_float2(acc[mi][ni][0], acc[mi][ni][1]);
            *(float2*)&C[(size_t)(r + 8) * N + c] =
                make_float2(acc[mi][ni][2], acc[mi][ni][3]);
        }
}

// ---- fused QKV GEMM: epilogue applies rope (+scale for q) and split-writes bf16
__global__ void __launch_bounds__(256, 1) gemm_qkv_kernel(
    const unsigned short* __restrict__ Ahi, const unsigned short* __restrict__ Alo,
    const unsigned short* __restrict__ Bhi, const unsigned short* __restrict__ Blo,
    const float* __restrict__ cs, const float* __restrict__ sn,
    unsigned short* __restrict__ qhi, unsigned short* __restrict__ qlo,
    unsigned short* __restrict__ khi, unsigned short* __restrict__ klo,
    unsigned short* __restrict__ vhi, unsigned short* __restrict__ vlo)
{
    GEMM_BODY(Ahi, Alo, Bhi, Blo, DMODEL)
    const int qid = lid >> 2, tq = lid & 3;
    const bool isV = (col0 >= QCOLS + KVCOLS);
    const bool isQ = (col0 < QCOLS);

    if (isV) {
#pragma unroll
        for (int mi = 0; mi < 4; mi++)
#pragma unroll
            for (int ni = 0; ni < 4; ni++) {
                int r = row0 + wm0 + mi * 16 + qid;
                int c = col0 - (QCOLS + KVCOLS) + wn0 + ni * 8 + tq * 2;
                uint32_t l0, l1;
                uint32_t h0 = split_pair(acc[mi][ni][0], acc[mi][ni][1], l0);
                uint32_t h1 = split_pair(acc[mi][ni][2], acc[mi][ni][3], l1);
                *(uint32_t*)(vhi + (size_t)r * KVCOLS + c) = h0;
                *(uint32_t*)(vlo + (size_t)r * KVCOLS + c) = l0;
                *(uint32_t*)(vhi + (size_t)(r + 8) * KVCOLS + c) = h1;
                *(uint32_t*)(vlo + (size_t)(r + 8) * KVCOLS + c) = l1;
            }
    } else {
        unsigned short* dh = isQ ? qhi : khi;
        unsigned short* dl = isQ ? qlo : klo;
        const int dcols = isQ ? QCOLS : KVCOLS;
        const int cbase = isQ ? col0 : col0 - QCOLS;
        const float scale = isQ ? QSCALE : 1.0f;
#pragma unroll
        for (int mi = 0; mi < 4; mi++) {
            int r = row0 + wm0 + mi * 16 + qid;
            int s0 = r & (S_LEN - 1);
            int s1 = (r + 8) & (S_LEN - 1);
#pragma unroll
            for (int ni = 0; ni < 4; ni++) {
                int c = cbase + wn0 + ni * 8 + tq * 2;
                int d2 = (c & 127) >> 1;
                float c0 = cs[s0 * 64 + d2], t0 = sn[s0 * 64 + d2];
                float c1 = cs[s1 * 64 + d2], t1 = sn[s1 * 64 + d2];
                float a0 = acc[mi][ni][0], a1 = acc[mi][ni][1];
                float a2 = acc[mi][ni][2], a3 = acc[mi][ni][3];
                float e0 = (a0 * c0 - a1 * t0) * scale;
                float e1 = (a0 * t0 + a1 * c0) * scale;
                float f0 = (a2 * c1 - a3 * t1) * scale;
                float f1 = (a2 * t1 + a3 * c1) * scale;
                uint32_t l0, l1;
                uint32_t h0 = split_pair(e0, e1, l0);
                uint32_t h1 = split_pair(f0, f1, l1);
                *(uint32_t*)(dh + (size_t)r * dcols + c) = h0;
                *(uint32_t*)(dl + (size_t)r * dcols + c) = l0;
                *(uint32_t*)(dh + (size_t)(r + 8) * dcols + c) = h1;
                *(uint32_t*)(dl + (size_t)(r + 8) * dcols + c) = l1;
            }
        }
    }
}

// ================= tensor-core flash attention (proven R8: BN=32) =================
#define AQ_STR   272
#define AT_MAT   (32 * AQ_STR)
#define AT_STAGE (4 * AT_MAT)
#define AT_SMEM  (2 * AT_STAGE)

__global__ void __launch_bounds__(256, 1) flash_mma_kernel(
    const unsigned short* __restrict__ qhi, const unsigned short* __restrict__ qlo,
    const unsigned short* __restrict__ khi, const unsigned short* __restrict__ klo,
    const unsigned short* __restrict__ vhi, const unsigned short* __restrict__ vlo,
    unsigned short* __restrict__ ohi, unsigned short* __restrict__ olo)
{
    extern __shared__ char smem[];
    const uint32_t sb = smem_u32(smem);
    const int tid = threadIdx.x;
    const int lid = tid & 31;
    const int wid = tid >> 5;
    const int qt = (int)gridDim.x - 1 - (int)blockIdx.x;
    const int h  = blockIdx.y;
    const int b  = blockIdx.z;
    const int g  = h >> 2;
    const int q0 = qt * 128;
    const int wm = wid * 16;

    const unsigned short* qh = qhi + ((size_t)(b * S_LEN + q0)) * QCOLS + h * HD;
    const unsigned short* ql = qlo + ((size_t)(b * S_LEN + q0)) * QCOLS + h * HD;
#pragma unroll
    for (int i = 0; i < 8; i++) {
        int cid = tid + 256 * i;
        int r = cid >> 4, c = cid & 15;
        uint32_t d = sb + r * AQ_STR + c * 16;
        size_t go = (size_t)r * QCOLS + c * 8;
        CP16(d, qh + go);
        CP16(d + AT_STAGE, ql + go);
    }
    CP_COMMIT(); CP_WAIT0();
    __syncthreads();

    uint32_t qfh[8][4], qfl[8][4];
#pragma unroll
    for (int kc = 0; kc < 8; kc++) {
        uint32_t addr = sb + (wm + (lid & 15)) * AQ_STR + (kc * 2 + (lid >> 4)) * 16;
        LDSM4(qfh[kc][0], qfh[kc][1], qfh[kc][2], qfh[kc][3], addr);
        LDSM4(qfl[kc][0], qfl[kc][1], qfl[kc][2], qfl[kc][3], addr + AT_STAGE);
    }
    __syncthreads();

    float o[16][4];
#pragma unroll
    for (int ni = 0; ni < 16; ni++)
#pragma unroll
        for (int c = 0; c < 4; c++) o[ni][c] = 0.f;
    float lsum0 = 0.f, lsum1 = 0.f;

    const unsigned short* kh = khi + (size_t)(b * S_LEN) * KVCOLS + g * HD;
    const unsigned short* kl = klo + (size_t)(b * S_LEN) * KVCOLS + g * HD;
    const unsigned short* vh = vhi + (size_t)(b * S_LEN) * KVCOLS + g * HD;
    const unsigned short* vl = vlo + (size_t)(b * S_LEN) * KVCOLS + g * HD;

    const int NKT = (qt + 1) * 4;

#define AT_LOAD(kt, st) do {                                                      \
    _Pragma("unroll")                                                             \
    for (int i = 0; i < 2; i++) {                                                 \
        int cid = tid + 256 * i;                                                  \
        int r = cid >> 4, c = cid & 15;                                           \
        uint32_t d = sb + (st) * AT_STAGE + r * AQ_STR + c * 16;                  \
        size_t go = (size_t)((kt) * 32 + r) * KVCOLS + c * 8;                     \
        CP16(d,              kh + go);                                            \
        CP16(d + AT_MAT,     kl + go);                                            \
        CP16(d + 2 * AT_MAT, vh + go);                                            \
        CP16(d + 3 * AT_MAT, vl + go);                                            \
    }                                                                             \
} while (0)

    AT_LOAD(0, 0);
    CP_COMMIT();

    const int r0 = q0 + wm + (lid >> 2);
    const int r1 = r0 + 8;

    for (int it = 0; it < NKT; ++it) {
        const int cur = it & 1;
        if (it + 1 < NKT) { AT_LOAD(it + 1, cur ^ 1); CP_COMMIT(); CP_WAIT1(); }
        else              { CP_WAIT0(); }
        __syncthreads();

        const int kv0 = it * 32;
        if (kv0 <= q0 + wm + 15) {
            const uint32_t base = sb + cur * AT_STAGE;

            float s[4][4];
#pragma unroll
            for (int ni = 0; ni < 4; ni++)
#pragma unroll
                for (int c = 0; c < 4; c++) s[ni][c] = 0.f;

#pragma unroll
            for (int kc = 0; kc < 8; kc++) {
                uint32_t bh_[4][2], bl_[4][2];
#pragma unroll
                for (int j = 0; j < 2; j++) {
                    int brow = j * 16 + (lid & 7) + ((lid >> 4) << 3);
                    uint32_t addr = base + brow * AQ_STR
                                  + kc * 32 + ((lid >> 3) & 1) * 16;
                    uint32_t t0, t1, t2, t3;
                    LDSM4(t0, t1, t2, t3, addr);
                    bh_[2 * j][0] = t0; bh_[2 * j][1] = t1;
                    bh_[2 * j + 1][0] = t2; bh_[2 * j + 1][1] = t3;
                    LDSM4(t0, t1, t2, t3, addr + AT_MAT);
                    bl_[2 * j][0] = t0; bl_[2 * j][1] = t1;
                    bl_[2 * j + 1][0] = t2; bl_[2 * j + 1][1] = t3;
                }
#pragma unroll
                for (int ni = 0; ni < 4; ni++) {
                    MMA16816(s[ni], qfh[kc], bh_[ni]);
                    MMA16816(s[ni], qfh[kc], bl_[ni]);
                    MMA16816(s[ni], qfl[kc], bh_[ni]);
                }
            }

            const bool need_mask = (kv0 + 31 > q0 + wm);
            uint32_t pa_h[2][4], pa_l[2][4];
#pragma unroll
            for (int ni = 0; ni < 4; ni++) {
                float s0 = fminf(s[ni][0], 60.f), s1 = fminf(s[ni][1], 60.f);
                float s2 = fminf(s[ni][2], 60.f), s3 = fminf(s[ni][3], 60.f);
                float p0, p1, p2, p3;
                if (need_mask) {
                    int cb = kv0 + ni * 8 + ((lid & 3) << 1);
                    p0 = (cb     <= r0) ? __expf(s0) : 0.f;
                    p1 = (cb + 1 <= r0) ? __expf(s1) : 0.f;
                    p2 = (cb     <= r1) ? __expf(s2) : 0.f;
                    p3 = (cb + 1 <= r1) ? __expf(s3) : 0.f;
                } else {
                    p0 = __expf(s0); p1 = __expf(s1);
                    p2 = __expf(s2); p3 = __expf(s3);
                }
                lsum0 += p0 + p1;
                lsum1 += p2 + p3;
                uint32_t lp01, lp23;
                uint32_t hp01 = split_pair(p0, p1, lp01);
                uint32_t hp23 = split_pair(p2, p3, lp23);
                int kc2 = ni >> 1, sel = (ni & 1) * 2;
                pa_h[kc2][sel]     = hp01;
                pa_h[kc2][sel + 1] = hp23;
                pa_l[kc2][sel]     = lp01;
                pa_l[kc2][sel + 1] = lp23;
            }

            const int gq = lid >> 3;
            const int vr = (gq & 1) * 8 + (lid & 7);
            const int vc = (gq >> 1) * 8;
#pragma unroll
            for (int j = 0; j < 8; j++) {
#pragma unroll
                for (int kc2 = 0; kc2 < 2; kc2++) {
                    uint32_t addr = base + 2 * AT_MAT
                                  + (kc2 * 16 + vr) * AQ_STR + (j * 16 + vc) * 2;
                    uint32_t t0, t1, t2, t3;
                    LDSM4T(t0, t1, t2, t3, addr);
                    uint32_t vb0[2] = {t0, t1}, vb1[2] = {t2, t3};
                    LDSM4T(t0, t1, t2, t3, addr + AT_MAT);
                    uint32_t wb0[2] = {t0, t1}, wb1[2] = {t2, t3};
                    MMA16816(o[2 * j],     pa_h[kc2], vb0);
                    MMA16816(o[2 * j],     pa_h[kc2], wb0);
                    MMA16816(o[2 * j],     pa_l[kc2], vb0);
                    MMA16816(o[2 * j + 1], pa_h[kc2], vb1);
                    MMA16816(o[2 * j + 1], pa_h[kc2], wb1);
                    MMA16816(o[2 * j + 1], pa_l[kc2], vb1);
                }
            }
        }
        __syncthreads();
    }
#undef AT_LOAD

    lsum0 += __shfl_xor_sync(0xffffffffu, lsum0, 1);
    lsum0 += __shfl_xor_sync(0xffffffffu, lsum0, 2);
    lsum1 += __shfl_xor_sync(0xffffffffu, lsum1, 1);
    lsum1 += __shfl_xor_sync(0xffffffffu, lsum1, 2);
    const float inv0 = 1.f / lsum0, inv1 = 1.f / lsum1;

    size_t r0g = (size_t)(b * S_LEN + r0) * QCOLS + h * HD;
    size_t r1g = r0g + (size_t)8 * QCOLS;
#pragma unroll
    for (int ni = 0; ni < 16; ni++) {
        int c = ni * 8 + ((lid & 3) << 1);
        uint32_t l0, l1;
        uint32_t h0 = split_pair(o[ni][0] * inv0, o[ni][1] * inv0, l0);
        uint32_t h1 = split_pair(o[ni][2] * inv1, o[ni][3] * inv1, l1);
        *(uint32_t*)(ohi + r0g + c) = h0;
        *(uint32_t*)(olo + r0g + c) = l0;
        *(uint32_t*)(ohi + r1g + c) = h1;
        *(uint32_t*)(olo + r1g + c) = l1;
    }
}

// ================= launch =================
extern "C" void kernel_launch(void* const* d_in, const int* in_sizes, int n_in,
                              void* d_out, int out_size)
{
    (void)in_sizes; (void)n_in; (void)out_size;
    const float* x  = (const float*)d_in[0];
    const float* fc = (const float*)d_in[1];
    const float* fs = (const float*)d_in[2];
    const float* wq = (const float*)d_in[3];
    const float* wk = (const float*)d_in[4];
    const float* wv = (const float*)d_in[5];
    const float* wo = (const float*)d_in[6];
    float* out = (float*)d_out;

    unsigned short *xhi, *xlo, *ahi, *alo, *qhi, *qlo, *khi, *klo, *vhi, *vlo;
    unsigned short *wqkvh, *wqkvl, *woh, *wol;
    cudaGetSymbolAddress((void**)&xhi,   g_xhi);
    cudaGetSymbolAddress((void**)&xlo,   g_xlo);
    cudaGetSymbolAddress((void**)&ahi,   g_ahi);
    cudaGetSymbolAddress((void**)&alo,   g_alo);
    cudaGetSymbolAddress((void**)&qhi,   g_qhi);
    cudaGetSymbolAddress((void**)&qlo,   g_qlo);
    cudaGetSymbolAddress((void**)&khi,   g_khi);
    cudaGetSymbolAddress((void**)&klo,   g_klo);
    cudaGetSymbolAddress((void**)&vhi,   g_vhi);
    cudaGetSymbolAddress((void**)&vlo,   g_vlo);
    cudaGetSymbolAddress((void**)&wqkvh, g_wqkvt_hi);
    cudaGetSymbolAddress((void**)&wqkvl, g_wqkvt_lo);
    cudaGetSymbolAddress((void**)&woh,   g_wot_hi);
    cudaGetSymbolAddress((void**)&wol,   g_wot_lo);

    cudaFuncSetAttribute(gemm_qkv_kernel,
                         cudaFuncAttributeMaxDynamicSharedMemorySize, GSMEM);
    cudaFuncSetAttribute(gemm_out_kernel,
                         cudaFuncAttributeMaxDynamicSharedMemorySize, GSMEM);
    cudaFuncSetAttribute(flash_mma_kernel,
                         cudaFuncAttributeMaxDynamicSharedMemorySize, AT_SMEM);

    // launch 0: split x
    {
        int n4 = M_ROWS * DMODEL / 4;
        split_kernel<<<(n4 + 255) / 256, 256>>>(x, xhi, xlo, n4);
    }
    // launch 1: fused transpose-split of all four weights
    tsplit_all_kernel<<<10240, dim3(32, 8)>>>(wq, wk, wv, wo,
                                              wqkvh, wqkvl, woh, wol);
    // launch 2: fused QKV projection + rope + split epilogue
    gemm_qkv_kernel<<<dim3(QKVN / BNN, M_ROWS / BMM), 256, GSMEM>>>(
        xhi, xlo, wqkvh, wqkvl, fc, fs, qhi, qlo, khi, klo, vhi, vlo);
    // launch 3: tensor-core flash attention
    flash_mma_kernel<<<dim3(S_LEN / 128, NH, BATCH), 256, AT_SMEM>>>(
        qhi, qlo, khi, klo, vhi, vlo, ahi, alo);
    // launch 4: out projection
    gemm_out_kernel<<<dim3(DMODEL / BNN, M_ROWS / BMM), 256, GSMEM>>>(
        ahi, alo, woh, wol, out, DMODEL, DMODEL);
}